// round 17
// baseline (speedup 1.0000x reference)
#include <cuda_runtime.h>
#include <math.h>

// ---------------- problem constants ----------------
#define Bb   16
#define Nn   785
#define Cc   768
#define Hh   12
#define Dd   64
#define Ss   79          // 1 CLS + 78 selected patches
#define NPp  784
#define KSEL 78
#define HSTR (Nn*Nn)          // head stride in attention_history
#define BSTR (Hh*Nn*Nn)       // batch stride
#define LSTR (Bb*Hh*Nn*Nn)    // layer stride
#define OUT1 (Bb*Nn*Cc)       // 9,646,080
#define OUT2 (Bb*Hh*Ss*Nn)    // 11,906,880
#define SCALE_F 0.125f        // 64^-0.5

// ---------------- device scratch (no allocations allowed) ----------------
__device__ float  g_e2[Bb*Nn];
__device__ float  g_v2[Bb*Nn];
__device__ float  g_r1[Bb*Nn];
__device__ float  g_r2[Bb];
__device__ float  g_E  [(size_t)Bb*Nn*Nn];
__device__ float  g_scoref[Bb*Nn];
__device__ int    g_sel[Bb*Ss];
__device__ float  g_k  [(size_t)Bb*Nn*Cc];
__device__ float  g_v  [(size_t)Bb*Nn*Cc];
__device__ float  g_qloc[Bb*Ss*Cc];
__device__ float  g_q  [Bb*Ss*Cc];
__device__ float  g_av [Bb*Ss*Cc];
__device__ float  g_o  [Bb*Ss*Cc];
__device__ float  g_attn_scratch[(size_t)Bb*Hh*Ss*Nn];

// ======================= FROZEN ROLLOUT PATH ==============================
// Everything from here to score_chain_kernel reproduces the reference's
// fp32 bit pattern (verified 8.9e-7 in r14/r15). DO NOT CHANGE ANY FP OP,
// REDUCTION ORDER, OR LAUNCH SHAPE IN THIS SECTION.

// ---------------- layer-0 E matrix: E[b,j,k] = fp32(0.5*mean_h + 0.5*I) ----
__global__ void build_E_kernel(const float* __restrict__ AH) {
    int j = blockIdx.x, b = blockIdx.y;
    const float* base = AH + (long)b*BSTR + (long)j*Nn;   // layer 0, row j
    float* erow = g_E + ((size_t)b*Nn + j)*Nn;
    for (int k = threadIdx.x; k < Nn; k += 256) {
        const float* p = base + k;
        float sh = 0.f;
        #pragma unroll
        for (int h = 0; h < Hh; h++) sh = __fadd_rn(sh, p[(long)h*HSTR]);
        float m = __fdiv_rn(sh, 12.0f);
        float e = __fmul_rn(0.5f, m);            // exact
        if (j == k) e = __fadd_rn(e, 0.5f);
        erow[k] = e;
    }
}

// ---------------- layer-1 row-0 e-values ----------------
__global__ void build_e2_kernel(const float* __restrict__ AH) {
    int b = blockIdx.y;
    int j = blockIdx.x * 256 + threadIdx.x;
    if (j >= Nn) return;
    const float* base = AH + (long)LSTR + (long)b*BSTR;   // layer 1, row 0
    float sh = 0.f;
    #pragma unroll
    for (int h = 0; h < Hh; h++) sh = __fadd_rn(sh, base[(long)h*HSTR + j]);
    float m = __fdiv_rn(sh, 12.0f);
    float e = __fmul_rn(0.5f, m);
    if (j == 0) e = __fadd_rn(e, 0.5f);
    g_e2[b*Nn + j] = e;
}

// ---------------- row reduction (r1, r2) — bits are selection-critical ----
__device__ __forceinline__ float warp_shfl_down_sum(float v) {
    v = __fadd_rn(v, __shfl_down_sync(0xffffffffu, v, 16));
    v = __fadd_rn(v, __shfl_down_sync(0xffffffffu, v, 8));
    v = __fadd_rn(v, __shfl_down_sync(0xffffffffu, v, 4));
    v = __fadd_rn(v, __shfl_down_sync(0xffffffffu, v, 2));
    v = __fadd_rn(v, __shfl_down_sync(0xffffffffu, v, 1));
    return v;
}

__global__ void rowsum_xla_kernel(const float* __restrict__ rows,
                                  float* __restrict__ out, int nrows) {
    int row = blockIdx.x;
    if (row >= nrows) return;
    int t = threadIdx.x;               // 0..1023
    float v = (t < Nn) ? rows[(size_t)row*Nn + t] : 0.f;
    v = warp_shfl_down_sum(v);
    __shared__ float s[32];
    if ((t & 31) == 0) s[t >> 5] = v;
    __syncthreads();
    if (t < 32) {
        float w = s[t];
        w = warp_shfl_down_sum(w);
        if (t == 0) out[row] = w;
    }
}

// ---------------- v2 = e2 / r2 ----------------
__global__ void v2_kernel() {
    int b = blockIdx.y;
    int j = blockIdx.x * 256 + threadIdx.x;
    if (j >= Nn) return;
    g_v2[b*Nn + j] = __fdiv_rn(g_e2[b*Nn + j], g_r2[b]);
}

// ---------------- scores: 2-lane interleaved (LLVM VF=2 reduction) --------
__global__ void score_chain_kernel() {
    int b = blockIdx.y;
    int k = blockIdx.x * 128 + threadIdx.x;
    if (k >= Nn) return;
    const float* Eb  = g_E + (size_t)b*Nn*Nn;
    const float* r1b = g_r1 + b*Nn;
    const float* v2b = g_v2 + b*Nn;
    float acc0 = 0.f, acc1 = 0.f;
    #pragma unroll 2
    for (int j = 0; j < NPp; j += 2) {
        float a0 = __fdiv_rn(Eb[(size_t)j*Nn + k],     r1b[j]);
        float a1 = __fdiv_rn(Eb[(size_t)(j+1)*Nn + k], r1b[j+1]);
        acc0 = __fmaf_rn(v2b[j],   a0, acc0);
        acc1 = __fmaf_rn(v2b[j+1], a1, acc1);
    }
    float c = __fadd_rn(acc0, acc1);
    float at = __fdiv_rn(Eb[(size_t)(Nn-1)*Nn + k], r1b[Nn-1]);
    c = __fmaf_rn(v2b[Nn-1], at, c);
    g_scoref[b*Nn + k] = c;
}
// ===================== END FROZEN ROLLOUT PATH ============================

// ---------------- top-k: one warp per batch, no barriers ------------------
// Selection semantics identical to reference: descending value, min index.
__global__ void topk_kernel() {   // grid Bb, block 32
    int b = blockIdx.x;
    int lane = threadIdx.x;
    float v[25];
    #pragma unroll
    for (int i = 0; i < 25; i++) {
        int p = lane + 32*i;
        v[i] = (p < NPp) ? g_scoref[b*Nn + 1 + p] : -INFINITY;
    }
    if (lane == 0) g_sel[b*Ss] = 0;   // CLS always first
    for (int it = 0; it < KSEL; it++) {
        float bv = -INFINITY; int bi = 1 << 30;
        #pragma unroll
        for (int i = 0; i < 25; i++) {
            if (v[i] > bv) { bv = v[i]; bi = lane + 32*i; }
        }
        #pragma unroll
        for (int off = 16; off > 0; off >>= 1) {
            float ov = __shfl_down_sync(0xffffffffu, bv, off);
            int   oi = __shfl_down_sync(0xffffffffu, bi, off);
            if (ov > bv || (ov == bv && oi < bi)) { bv = ov; bi = oi; }
        }
        bi = __shfl_sync(0xffffffffu, bi, 0);
        if (lane == (bi & 31)) {
            int ii = bi >> 5;
            #pragma unroll
            for (int i = 0; i < 25; i++) if (i == ii) v[i] = -INFINITY;
        }
        if (lane == 0) g_sel[b*Ss + 1 + it] = bi + 1;
    }
}

// ---------------- gather selected x rows (float4) ----------------
__global__ void gather_kernel(const float* __restrict__ x) {
    int s = blockIdx.x, b = blockIdx.y;
    int tok = g_sel[b*Ss + s];
    const float4* src = (const float4*)(x + ((long)b*Nn + tok)*Cc);
    float4* dst = (float4*)(g_qloc + ((long)b*Ss + s)*Cc);
    for (int c = threadIdx.x; c < Cc/4; c += blockDim.x) dst[c] = src[c];
}

// ================= TF32 tensor-core NT GEMM (3xTF32, double-buffered) =====
__device__ __forceinline__ void tf32_split(float x, unsigned& hi, unsigned& lo) {
    unsigned h;
    asm("cvt.rna.tf32.f32 %0, %1;" : "=r"(h) : "f"(x));
    float hf = __uint_as_float(h);
    float r = x - hf;
    unsigned l;
    asm("cvt.rna.tf32.f32 %0, %1;" : "=r"(l) : "f"(r));
    hi = h; lo = l;
}

#define MMA_TF32(d, a0,a1,a2,a3, b0,b1)                                       \
    asm volatile("mma.sync.aligned.m16n8k8.row.col.f32.tf32.tf32.f32 "        \
        "{%0,%1,%2,%3}, {%4,%5,%6,%7}, {%8,%9}, {%0,%1,%2,%3};"               \
        : "+f"(d[0]), "+f"(d[1]), "+f"(d[2]), "+f"(d[3])                      \
        : "r"(a0), "r"(a1), "r"(a2), "r"(a3), "r"(b0), "r"(b1))

#define SMEM_GEMM_BYTES (2*(128*17 + 64*17) * (int)sizeof(uint2))   // 52224

__global__ __launch_bounds__(256)
void gemm_tf32_nt(const float* __restrict__ A, const float* __restrict__ Bm,
                  float* __restrict__ C, int M, int N, int K,
                  const float* __restrict__ bias)
{
    extern __shared__ uint2 smz[];
    uint2* Asb = smz;                    // 2 * 128 * 17
    uint2* Bsb = smz + 2*128*17;         // 2 * 64 * 17
#define AS(bf,m,k) Asb[(bf)*128*17 + (m)*17 + (k)]
#define BS(bf,n,k) Bsb[(bf)*64*17  + (n)*17 + (k)]

    int tid = threadIdx.x;
    int lane = tid & 31, wid = tid >> 5;
    int wm = wid & 3, wn = wid >> 2;
    int m0 = blockIdx.y * 128, n0 = blockIdx.x * 64;
    int wmb = wm * 32, wnb = wn * 32;
    int lq = lane >> 2, lr = lane & 3;

    float acc[2][4][4];
    #pragma unroll
    for (int i = 0; i < 2; i++)
        #pragma unroll
        for (int j = 0; j < 4; j++)
            #pragma unroll
            for (int c = 0; c < 4; c++) acc[i][j][c] = 0.f;

    int amA0 = (tid + 0)   >> 2, akA0 = ((tid + 0)   & 3) * 4;
    int amA1 = (tid + 256) >> 2, akA1 = ((tid + 256) & 3) * 4;
    int bn   = tid >> 2,        bk   = (tid & 3) * 4;

    float4 ra0, ra1, rb;
    {
        int gm0 = m0 + amA0, gm1 = m0 + amA1;
        ra0 = (gm0 < M) ? *(const float4*)(A + (size_t)gm0*K + akA0) : make_float4(0,0,0,0);
        ra1 = (gm1 < M) ? *(const float4*)(A + (size_t)gm1*K + akA1) : make_float4(0,0,0,0);
        rb  = *(const float4*)(Bm + (size_t)(n0 + bn)*K + bk);
    }
    {
        unsigned h, l;
        tf32_split(ra0.x, h, l); AS(0, amA0, akA0+0) = make_uint2(h, l);
        tf32_split(ra0.y, h, l); AS(0, amA0, akA0+1) = make_uint2(h, l);
        tf32_split(ra0.z, h, l); AS(0, amA0, akA0+2) = make_uint2(h, l);
        tf32_split(ra0.w, h, l); AS(0, amA0, akA0+3) = make_uint2(h, l);
        tf32_split(ra1.x, h, l); AS(0, amA1, akA1+0) = make_uint2(h, l);
        tf32_split(ra1.y, h, l); AS(0, amA1, akA1+1) = make_uint2(h, l);
        tf32_split(ra1.z, h, l); AS(0, amA1, akA1+2) = make_uint2(h, l);
        tf32_split(ra1.w, h, l); AS(0, amA1, akA1+3) = make_uint2(h, l);
        tf32_split(rb.x,  h, l); BS(0, bn, bk+0) = make_uint2(h, l);
        tf32_split(rb.y,  h, l); BS(0, bn, bk+1) = make_uint2(h, l);
        tf32_split(rb.z,  h, l); BS(0, bn, bk+2) = make_uint2(h, l);
        tf32_split(rb.w,  h, l); BS(0, bn, bk+3) = make_uint2(h, l);
    }
    __syncthreads();

    int nk = K / 16;
    for (int t = 0; t < nk; t++) {
        int buf = t & 1;
        bool more = (t + 1 < nk);
        if (more) {
            int k0 = (t + 1) * 16;
            int gm0 = m0 + amA0, gm1 = m0 + amA1;
            ra0 = (gm0 < M) ? *(const float4*)(A + (size_t)gm0*K + k0 + akA0) : make_float4(0,0,0,0);
            ra1 = (gm1 < M) ? *(const float4*)(A + (size_t)gm1*K + k0 + akA1) : make_float4(0,0,0,0);
            rb  = *(const float4*)(Bm + (size_t)(n0 + bn)*K + k0 + bk);
        }
        #pragma unroll
        for (int ks = 0; ks < 16; ks += 8) {
            uint2 a2[2][4], b2[4][2];
            #pragma unroll
            for (int fm = 0; fm < 2; fm++) {
                int mr = wmb + fm*16 + lq;
                a2[fm][0] = AS(buf, mr,   ks+lr);
                a2[fm][1] = AS(buf, mr+8, ks+lr);
                a2[fm][2] = AS(buf, mr,   ks+lr+4);
                a2[fm][3] = AS(buf, mr+8, ks+lr+4);
            }
            #pragma unroll
            for (int fn = 0; fn < 4; fn++) {
                int nc = wnb + fn*8 + lq;
                b2[fn][0] = BS(buf, nc, ks+lr);
                b2[fn][1] = BS(buf, nc, ks+lr+4);
            }
            #pragma unroll
            for (int fm = 0; fm < 2; fm++)
                #pragma unroll
                for (int fn = 0; fn < 4; fn++) {
                    MMA_TF32(acc[fm][fn], a2[fm][0].x, a2[fm][1].x, a2[fm][2].x, a2[fm][3].x,
                                           b2[fn][0].x, b2[fn][1].x);
                    MMA_TF32(acc[fm][fn], a2[fm][0].x, a2[fm][1].x, a2[fm][2].x, a2[fm][3].x,
                                           b2[fn][0].y, b2[fn][1].y);
                    MMA_TF32(acc[fm][fn], a2[fm][0].y, a2[fm][1].y, a2[fm][2].y, a2[fm][3].y,
                                           b2[fn][0].x, b2[fn][1].x);
                }
        }
        if (more) {
            int nb = buf ^ 1;
            unsigned h, l;
            tf32_split(ra0.x, h, l); AS(nb, amA0, akA0+0) = make_uint2(h, l);
            tf32_split(ra0.y, h, l); AS(nb, amA0, akA0+1) = make_uint2(h, l);
            tf32_split(ra0.z, h, l); AS(nb, amA0, akA0+2) = make_uint2(h, l);
            tf32_split(ra0.w, h, l); AS(nb, amA0, akA0+3) = make_uint2(h, l);
            tf32_split(ra1.x, h, l); AS(nb, amA1, akA1+0) = make_uint2(h, l);
            tf32_split(ra1.y, h, l); AS(nb, amA1, akA1+1) = make_uint2(h, l);
            tf32_split(ra1.z, h, l); AS(nb, amA1, akA1+2) = make_uint2(h, l);
            tf32_split(ra1.w, h, l); AS(nb, amA1, akA1+3) = make_uint2(h, l);
            tf32_split(rb.x,  h, l); BS(nb, bn, bk+0) = make_uint2(h, l);
            tf32_split(rb.y,  h, l); BS(nb, bn, bk+1) = make_uint2(h, l);
            tf32_split(rb.z,  h, l); BS(nb, bn, bk+2) = make_uint2(h, l);
            tf32_split(rb.w,  h, l); BS(nb, bn, bk+3) = make_uint2(h, l);
        }
        __syncthreads();
    }

    #pragma unroll
    for (int fm = 0; fm < 2; fm++) {
        int r0 = m0 + wmb + fm*16 + lq;
        #pragma unroll
        for (int fn = 0; fn < 4; fn++) {
            int cb = n0 + wnb + fn*8 + lr*2;
            float b0 = bias ? bias[cb]   : 0.f;
            float b1 = bias ? bias[cb+1] : 0.f;
            if (r0 < M) {
                C[(size_t)r0*N + cb]   = acc[fm][fn][0] + b0;
                C[(size_t)r0*N + cb+1] = acc[fm][fn][1] + b1;
            }
            if (r0 + 8 < M) {
                C[(size_t)(r0+8)*N + cb]   = acc[fm][fn][2] + b0;
                C[(size_t)(r0+8)*N + cb+1] = acc[fm][fn][3] + b1;
            }
        }
    }
#undef AS
#undef BS
}

// ---------------- generic batched-strided GEMM (FFMA; small shapes) -------
template<bool BT>
__global__ void gemm128_kernel(const float* __restrict__ Ag,
                               const float* __restrict__ Bg,
                               float* __restrict__ Cg,
                               int M, int Ncols, int K,
                               int lda, int ldb, int ldc,
                               long sAb, long sAh, long sBb, long sBh,
                               long sCb, long sCh, int Hdim,
                               const float* __restrict__ bias, float alpha)
{
    const int BM = 128, BN = 128, BK = 16;
    int z  = blockIdx.z;
    int zb = z / Hdim, zh = z % Hdim;
    const float* A = Ag + zb*sAb + zh*sAh;
    const float* Bp = Bg + zb*sBb + zh*sBh;
    float* C = Cg + zb*sCb + zh*sCh;
    int m0 = blockIdx.y * BM;
    int n0 = blockIdx.x * BN;

    __shared__ float As[BK][BM];
    __shared__ float Bs[BK][BN];

    int tid = threadIdx.x;
    int tx = tid & 15, ty = tid >> 4;
    float acc[8][8];
    #pragma unroll
    for (int i = 0; i < 8; i++)
        #pragma unroll
        for (int j = 0; j < 8; j++) acc[i][j] = 0.f;

    for (int k0 = 0; k0 < K; k0 += BK) {
        #pragma unroll
        for (int idx = tid; idx < BM*BK; idx += 256) {
            int mm = idx >> 4, kk = idx & 15;
            int gm = m0 + mm, gk = k0 + kk;
            float v = 0.f;
            if (gm < M && gk < K) v = A[(long)gm*lda + gk];
            As[kk][mm] = v;
        }
        #pragma unroll
        for (int idx = tid; idx < BN*BK; idx += 256) {
            int nn, kk;
            if (BT) { nn = idx >> 4; kk = idx & 15; }
            else    { kk = idx >> 7; nn = idx & 127; }
            int gn = n0 + nn, gk = k0 + kk;
            float v = 0.f;
            if (gn < Ncols && gk < K)
                v = BT ? Bp[(long)gn*ldb + gk] : Bp[(long)gk*ldb + gn];
            Bs[kk][nn] = v;
        }
        __syncthreads();
        #pragma unroll
        for (int kk = 0; kk < BK; kk++) {
            float a[8], bb[8];
            #pragma unroll
            for (int i = 0; i < 8; i++) a[i] = As[kk][ty*8 + i];
            #pragma unroll
            for (int j = 0; j < 8; j++) bb[j] = Bs[kk][tx*8 + j];
            #pragma unroll
            for (int i = 0; i < 8; i++)
                #pragma unroll
                for (int j = 0; j < 8; j++) acc[i][j] += a[i]*bb[j];
        }
        __syncthreads();
    }

    #pragma unroll
    for (int i = 0; i < 8; i++) {
        int gm = m0 + ty*8 + i;
        if (gm >= M) continue;
        #pragma unroll
        for (int j = 0; j < 8; j++) {
            int gn = n0 + tx*8 + j;
            if (gn >= Ncols) continue;
            float v = acc[i][j]*alpha;
            if (bias) v += bias[gn];
            C[(long)gm*ldc + gn] = v;
        }
    }
}

// ---------------- softmax over rows of length N ----------------
__global__ void softmax_kernel(float* __restrict__ P) {
    long row = blockIdx.x;
    float* d = P + row*(long)Nn;
    int tid = threadIdx.x;
    __shared__ float red[256];

    float mx = -INFINITY;
    for (int i = tid; i < Nn; i += 256) { float v = d[i]; mx = v > mx ? v : mx; }
    red[tid] = mx; __syncthreads();
    for (int off = 128; off > 0; off >>= 1) {
        if (tid < off && red[tid+off] > red[tid]) red[tid] = red[tid+off];
        __syncthreads();
    }
    mx = red[0]; __syncthreads();

    float sum = 0.f;
    for (int i = tid; i < Nn; i += 256) {
        float e = expf(d[i] - mx);
        d[i] = e;
        sum += e;
    }
    red[tid] = sum; __syncthreads();
    for (int off = 128; off > 0; off >>= 1) {
        if (tid < off) red[tid] += red[tid+off];
        __syncthreads();
    }
    float inv = 1.0f / red[0];
    for (int i = tid; i < Nn; i += 256) d[i] *= inv;
}

// ---------------- zero + scatter ----------------
__global__ void zero_kernel(float4* __restrict__ p, long n4) {
    long i = (long)blockIdx.x * blockDim.x + threadIdx.x;
    if (i < n4) p[i] = make_float4(0.f, 0.f, 0.f, 0.f);
}

__global__ void scatter_kernel(float* __restrict__ out) {
    int s = blockIdx.x, b = blockIdx.y;
    int tok = g_sel[b*Ss + s];
    const float4* src = (const float4*)(g_o + ((long)b*Ss + s)*Cc);
    float4* dst = (float4*)(out + ((long)b*Nn + tok)*Cc);
    for (int c = threadIdx.x; c < Cc/4; c += blockDim.x) dst[c] = src[c];
}

// ---------------- launch ----------------
extern "C" void kernel_launch(void* const* d_in, const int* in_sizes, int n_in,
                              void* d_out, int out_size) {
    const float* x  = (const float*)d_in[0];
    const float* AH = (const float*)d_in[1];
    const float* Wq = (const float*)d_in[2];
    const float* bq = (const float*)d_in[3];
    const float* Wk = (const float*)d_in[4];
    const float* bk = (const float*)d_in[5];
    const float* Wv = (const float*)d_in[6];
    const float* bv = (const float*)d_in[7];
    const float* Wo = (const float*)d_in[8];
    const float* bo = (const float*)d_in[9];
    float* out = (float*)d_out;

    float *pk, *pv, *pqloc, *pq, *pav, *po, *pattn_s, *pE, *pe2, *pr1, *pr2;
    cudaGetSymbolAddress((void**)&pk,      g_k);
    cudaGetSymbolAddress((void**)&pv,      g_v);
    cudaGetSymbolAddress((void**)&pqloc,   g_qloc);
    cudaGetSymbolAddress((void**)&pq,      g_q);
    cudaGetSymbolAddress((void**)&pav,     g_av);
    cudaGetSymbolAddress((void**)&po,      g_o);
    cudaGetSymbolAddress((void**)&pattn_s, g_attn_scratch);
    cudaGetSymbolAddress((void**)&pE,      g_E);
    cudaGetSymbolAddress((void**)&pe2,     g_e2);
    cudaGetSymbolAddress((void**)&pr1,     g_r1);
    cudaGetSymbolAddress((void**)&pr2,     g_r2);

    cudaFuncSetAttribute(gemm_tf32_nt,
                         cudaFuncAttributeMaxDynamicSharedMemorySize,
                         SMEM_GEMM_BYTES);

    float* attnP = (out_size >= OUT1 + OUT2) ? (out + OUT1) : pattn_s;

    // ---- rollout (FROZEN r14/r15 pipeline) ----
    build_E_kernel<<<dim3(Nn, Bb), 256>>>(AH);
    build_e2_kernel<<<dim3((Nn+255)/256, Bb), 256>>>(AH);
    rowsum_xla_kernel<<<Bb*Nn, 1024>>>(pE, pr1, Bb*Nn);   // r1 rows of E
    rowsum_xla_kernel<<<Bb, 1024>>>(pe2, pr2, Bb);        // r2
    v2_kernel<<<dim3((Nn+255)/256, Bb), 256>>>();
    score_chain_kernel<<<dim3((Nn+127)/128, Bb), 128>>>();
    topk_kernel<<<Bb, 32>>>();
    gather_kernel<<<dim3(Ss, Bb), 256>>>(x);

    // ---- projections on tensor cores (3xTF32, double-buffered) ----
    {
        dim3 g(Cc/64, (Bb*Nn + 127)/128);
        gemm_tf32_nt<<<g, 256, SMEM_GEMM_BYTES>>>(x, Wk, pk, Bb*Nn, Cc, Cc, bk);
        gemm_tf32_nt<<<g, 256, SMEM_GEMM_BYTES>>>(x, Wv, pv, Bb*Nn, Cc, Cc, bv);
    }
    {
        dim3 g(Cc/64, (Bb*Ss + 127)/128);
        gemm_tf32_nt<<<g, 256, SMEM_GEMM_BYTES>>>(pqloc, Wq, pq, Bb*Ss, Cc, Cc, bq);
    }

    // ---- logits: attn[b,h,s,n] = SCALE * q . k  (batched NT) ----
    {
        dim3 g((Nn+127)/128, 1, Bb*Hh);
        gemm128_kernel<true><<<g, 256>>>(pq, pk, attnP,
                                         Ss, Nn, Dd,
                                         Cc, Cc, Nn,
                                         (long)Ss*Cc, (long)Dd,
                                         (long)Nn*Cc, (long)Dd,
                                         (long)Hh*Ss*Nn, (long)Ss*Nn, Hh,
                                         nullptr, SCALE_F);
    }

    // ---- softmax rows (this IS the attn_weights output) ----
    softmax_kernel<<<Bb*Hh*Ss, 256>>>(attnP);

    // ---- AV: out[b,h,s,d] = P @ V  (batched NN) ----
    {
        dim3 g(1, 1, Bb*Hh);
        gemm128_kernel<false><<<g, 256>>>(attnP, pv, pav,
                                          Ss, Dd, Nn,
                                          Nn, Cc, Cc,
                                          (long)Hh*Ss*Nn, (long)Ss*Nn,
                                          (long)Nn*Cc, (long)Dd,
                                          (long)Ss*Cc, (long)Dd, Hh,
                                          nullptr, 1.0f);
    }

    // ---- output projection on tensor cores ----
    {
        dim3 g(Cc/64, (Bb*Ss + 127)/128);
        gemm_tf32_nt<<<g, 256, SMEM_GEMM_BYTES>>>(pav, Wo, po, Bb*Ss, Cc, Cc, bo);
    }

    // ---- scatter into zeroed token grid ----
    zero_kernel<<<(OUT1/4 + 255)/256, 256>>>((float4*)out, (long)(OUT1/4));
    scatter_kernel<<<dim3(Ss, Bb), 256>>>(out);
}